// round 13
// baseline (speedup 1.0000x reference)
#include <cuda_runtime.h>
#include <cuda_bf16.h>
#include <cstddef>

// ============================================================================
// MiniQuixerPQCBlock — exact MPS (bond dim 16), warp-register environments.
// R12: pass-pairs merged into 2-bit rounds with hoisted shfl volleys:
// per site = W (in-thread, no shfl) + round(1,2) + round(4,8) + round(16),
// i.e. 3 shfl stall-rounds instead of 5, 4 dependency rounds instead of 7.
// ============================================================================

__device__ __forceinline__ float2 cmul(float2 a, float2 b) {
    return make_float2(fmaf(a.x, b.x, -a.y * b.y), fmaf(a.x, b.y, a.y * b.x));
}
__device__ __forceinline__ float2 cfma(float2 a, float2 b, float2 c) {      // c += a*b
    c.x = fmaf(a.x, b.x, fmaf(-a.y, b.y, c.x));
    c.y = fmaf(a.x, b.y, fmaf(a.y, b.x, c.y));
    return c;
}
__device__ __forceinline__ float2 cmulc(float2 a, float2 b) {               // a*conj(b)
    return make_float2(fmaf(a.x, b.x, a.y * b.y), fmaf(a.y, b.x, -a.x * b.y));
}
__device__ __forceinline__ float2 cfmac(float2 a, float2 b, float2 c) {     // c += a*conj(b)
    c.x = fmaf(a.x, b.x, fmaf(a.y, b.y, c.x));
    c.y = fmaf(a.y, b.x, fmaf(-a.x, b.y, c.y));
    return c;
}
__device__ __forceinline__ float2 shflx(float2 v, int m) {
    v.x = __shfl_xor_sync(0xffffffffu, v.x, m);
    v.y = __shfl_xor_sync(0xffffffffu, v.y, m);
    return v;
}

struct Env { float2 e00, e01, e10, e11; };  // e[r1][r0]

__device__ __forceinline__ Env shfl_env(const Env& E, int m) {
    Env P;
    P.e00 = shflx(E.e00, m); P.e01 = shflx(E.e01, m);
    P.e10 = shflx(E.e10, m); P.e11 = shflx(E.e11, m);
    return P;
}

// merged in-thread pass over (r0 ket, r1 bra): q_{dk,db} = w[dk]*conj(w[db])
__device__ __forceinline__ void roundW(Env& E, float2 w0, float2 w1) {
    float2 q00 = cmulc(w0, w0), q01 = cmulc(w0, w1);
    float2 q10 = cmulc(w1, w0), q11 = cmulc(w1, w1);
    float2 o00 = cfma(q11, E.e11, cfma(q01, E.e10, cfma(q10, E.e01, cmul(q00, E.e00))));
    float2 o01 = cfma(q01, E.e11, cfma(q11, E.e10, cfma(q00, E.e01, cmul(q10, E.e00))));
    float2 o10 = cfma(q10, E.e11, cfma(q00, E.e10, cfma(q11, E.e01, cmul(q01, E.e00))));
    float2 o11 = cfma(q00, E.e11, cfma(q10, E.e10, cfma(q01, E.e01, cmul(q11, E.e00))));
    E.e00 = o00; E.e01 = o01; E.e10 = o10; E.e11 = o11;
}

// merged lane round over masks (1,2): ket gates per r0 (k0,k2 | k1,k3),
// bra conj gates per r1 (same table). Neighbors hoisted in one volley.
__device__ __forceinline__ void roundA(Env& E, float2 k0, float2 k2, float2 k1, float2 k3) {
    Env n1 = shfl_env(E, 1), n2 = shfl_env(E, 2), n3 = shfl_env(E, 3);
    Env t0, t1;
    t0.e00 = cfma(k2, n1.e00, cmul(k0, E.e00));
    t0.e10 = cfma(k2, n1.e10, cmul(k0, E.e10));
    t0.e01 = cfma(k3, n1.e01, cmul(k1, E.e01));
    t0.e11 = cfma(k3, n1.e11, cmul(k1, E.e11));
    t1.e00 = cfma(k2, n3.e00, cmul(k0, n2.e00));
    t1.e10 = cfma(k2, n3.e10, cmul(k0, n2.e10));
    t1.e01 = cfma(k3, n3.e01, cmul(k1, n2.e01));
    t1.e11 = cfma(k3, n3.e11, cmul(k1, n2.e11));
    E.e00 = cfmac(t1.e00, k2, cmulc(t0.e00, k0));
    E.e01 = cfmac(t1.e01, k2, cmulc(t0.e01, k0));
    E.e10 = cfmac(t1.e10, k3, cmulc(t0.e10, k1));
    E.e11 = cfmac(t1.e11, k3, cmulc(t0.e11, k1));
}

// merged lane round over masks (4,8): uniform ket gates (g0 self, g1 partner),
// uniform bra conj gates (h0 self, h1 partner).
__device__ __forceinline__ void roundB(Env& E, float2 g0, float2 g1, float2 h0, float2 h1) {
    Env n4 = shfl_env(E, 4), n8 = shfl_env(E, 8), n12 = shfl_env(E, 12);
    Env t0, t1;
    t0.e00 = cfma(g1, n4.e00, cmul(g0, E.e00));
    t0.e01 = cfma(g1, n4.e01, cmul(g0, E.e01));
    t0.e10 = cfma(g1, n4.e10, cmul(g0, E.e10));
    t0.e11 = cfma(g1, n4.e11, cmul(g0, E.e11));
    t1.e00 = cfma(g1, n12.e00, cmul(g0, n8.e00));
    t1.e01 = cfma(g1, n12.e01, cmul(g0, n8.e01));
    t1.e10 = cfma(g1, n12.e10, cmul(g0, n8.e10));
    t1.e11 = cfma(g1, n12.e11, cmul(g0, n8.e11));
    E.e00 = cfmac(t1.e00, h1, cmulc(t0.e00, h0));
    E.e01 = cfmac(t1.e01, h1, cmulc(t0.e01, h0));
    E.e10 = cfmac(t1.e10, h1, cmulc(t0.e10, h0));
    E.e11 = cfmac(t1.e11, h1, cmulc(t0.e11, h0));
}

// single lane pass over mask 16, uniform plain gates
__device__ __forceinline__ void roundC(Env& E, float2 gA, float2 gB) {
    Env P = shfl_env(E, 16);
    E.e00 = cfma(gB, P.e00, cmul(gA, E.e00));
    E.e01 = cfma(gB, P.e01, cmul(gA, E.e01));
    E.e10 = cfma(gB, P.e10, cmul(gA, E.e10));
    E.e11 = cfma(gB, P.e11, cmul(gA, E.e11));
}

__global__ __launch_bounds__(64) void pqc_mps_kernel(
    const float* __restrict__ ctx,   // [B, 256]
    const float* __restrict__ Wm,    // [16, 256]
    const float* __restrict__ bv,    // [16]
    const float* __restrict__ prm,   // [4, 16, 3]
    float* __restrict__ out)         // [B, 16]
{
    __shared__ __align__(16) float4 Lsm[17][2][32];
    __shared__ __align__(16) float4 Rsm[17][2][32];
    __shared__ __align__(16) float2 Usm[4][16][4];   // [layer][wire][d*2+c]
    __shared__ __align__(16) float2 wsm[16][2];
    __shared__ float pf[16];

    const int tid  = threadIdx.x;
    const int lane = tid & 31;
    const int warp = tid >> 5;
    const int bat  = blockIdx.x;

    // ---------- setup: encoding dots + fused gates ----------
    {
        int q = tid >> 2, quarter = tid & 3;
        const float4* cr = (const float4*)(ctx + (size_t)bat * 256) + quarter * 16;
        const float4* wr = (const float4*)(Wm + (size_t)q * 256) + quarter * 16;
        float acc = 0.f;
        #pragma unroll
        for (int k = 0; k < 16; ++k) {
            float4 c = cr[k], w = wr[k];
            acc = fmaf(c.x, w.x, acc); acc = fmaf(c.y, w.y, acc);
            acc = fmaf(c.z, w.z, acc); acc = fmaf(c.w, w.w, acc);
        }
        acc += __shfl_xor_sync(0xffffffffu, acc, 1);
        acc += __shfl_xor_sync(0xffffffffu, acc, 2);
        if (quarter == 0) pf[q] = acc;
    }
    {
        int l = tid >> 4, q = tid & 15;
        const float* p = prm + (size_t)(l * 16 + q) * 3;
        float ca = cosf(0.5f * p[0]), sa = sinf(0.5f * p[0]);
        float cb = cosf(0.5f * p[1]), sb = sinf(0.5f * p[1]);
        float cg = cosf(0.5f * p[2]), sg = sinf(0.5f * p[2]);
        float2 X00 = make_float2(ca, 0.f), X01 = make_float2(0.f, -sa);
        float2 M00 = make_float2(cb * X00.x - sb * X01.x, cb * X00.y - sb * X01.y);
        float2 M01 = make_float2(cb * X01.x - sb * X00.x, cb * X01.y - sb * X00.y);
        float2 M10 = make_float2(sb * X00.x + cb * X01.x, sb * X00.y + cb * X01.y);
        float2 M11 = make_float2(sb * X01.x + cb * X00.x, sb * X01.y + cb * X00.y);
        float2 em = make_float2(cg, -sg), ep = make_float2(cg, sg);
        Usm[l][q][0] = cmul(em, M00);
        Usm[l][q][1] = cmul(em, M01);
        Usm[l][q][2] = cmul(ep, M10);
        Usm[l][q][3] = cmul(ep, M11);
    }
    __syncthreads();
    if (tid < 16) {
        float ang = 3.14159265358979323846f * tanhf(pf[tid] + bv[tid]);
        float h = 0.5f * ang;
        float2 v0 = make_float2(cosf(h), 0.f);
        float2 v1 = make_float2(0.f, -sinf(h));
        wsm[tid][0] = cfma(Usm[0][tid][1], v1, cmul(Usm[0][tid][0], v0));
        wsm[tid][1] = cfma(Usm[0][tid][3], v1, cmul(Usm[0][tid][2], v0));
    }
    __syncthreads();

    const int l0 = lane & 1, l1 = (lane >> 1) & 1;
    const int l2 = (lane >> 2) & 1, l3 = (lane >> 3) & 1;

    if (warp == 0) {
        // =============== LEFT SWEEP: L_0 -> L_16 ===============
        Env E;
        float2 z = make_float2(0.f, 0.f);
        E.e00 = make_float2(lane == 0 ? 1.f : 0.f, 0.f);
        E.e01 = z; E.e10 = z; E.e11 = z;

        #pragma unroll 2
        for (int q = 0; q < 16; ++q) {
            float4 wv = *(const float4*)wsm[q];
            float2 w0 = make_float2(wv.x, wv.y), w1 = make_float2(wv.z, wv.w);
            const float4* U2p = (const float4*)Usm[1][q];
            float4 u2a = U2p[0], u2b = U2p[1];
            const float4* U3p = (const float4*)Usm[2][q];
            float4 u3a = U3p[0], u3b = U3p[1];
            const float4* U4p = (const float4*)Usm[3][q];
            float4 u4a = U4p[0], u4b = U4p[1];
            float2 U2t[4] = { make_float2(u2a.x, u2a.y), make_float2(u2a.z, u2a.w),
                              make_float2(u2b.x, u2b.y), make_float2(u2b.z, u2b.w) };
            float2 U3t[4] = { make_float2(u3a.x, u3a.y), make_float2(u3a.z, u3a.w),
                              make_float2(u3b.x, u3b.y), make_float2(u3b.z, u3b.w) };
            float2 U4t[4] = { make_float2(u4a.x, u4a.y), make_float2(u4a.z, u4a.w),
                              make_float2(u4b.x, u4b.y), make_float2(u4b.z, u4b.w) };
            roundW(E, w0, w1);                                    // z1,zp1 -> b1,bp1
            roundA(E, U2t[0], U2t[2], U2t[1], U2t[3]);            // z2,zp2 -> b2,bp2
            roundB(E, U3t[l0], U3t[2 | l0], U3t[l1], U3t[2 | l1]);// z3,zp3 -> b3,bp3
            float2 G0 = cmulc(U4t[l2], U4t[l3]);                  // j -> jn
            float2 G1 = cmulc(U4t[2 | l2], U4t[2 | l3]);
            roundC(E, G0, G1);
            Lsm[q + 1][0][lane] = make_float4(E.e00.x, E.e00.y, E.e01.x, E.e01.y);
            Lsm[q + 1][1][lane] = make_float4(E.e10.x, E.e10.y, E.e11.x, E.e11.y);
        }
    } else {
        // =============== RIGHT SWEEP: R_16 -> R_1 ===============
        Env E;
        float2 one = make_float2(1.f, 0.f);
        E.e00 = one; E.e01 = one; E.e10 = one; E.e11 = one;
        Rsm[16][0][lane] = make_float4(1.f, 0.f, 1.f, 0.f);
        Rsm[16][1][lane] = make_float4(1.f, 0.f, 1.f, 0.f);

        #pragma unroll 2
        for (int q = 15; q >= 1; --q) {
            float4 wv = *(const float4*)wsm[q];
            float2 w0 = make_float2(wv.x, wv.y), w1 = make_float2(wv.z, wv.w);
            const float4* U2p = (const float4*)Usm[1][q];
            float4 u2a = U2p[0], u2b = U2p[1];
            const float4* U3p = (const float4*)Usm[2][q];
            float4 u3a = U3p[0], u3b = U3p[1];
            const float4* U4p = (const float4*)Usm[3][q];
            float4 u4a = U4p[0], u4b = U4p[1];
            float2 U2t[4] = { make_float2(u2a.x, u2a.y), make_float2(u2a.z, u2a.w),
                              make_float2(u2b.x, u2b.y), make_float2(u2b.z, u2b.w) };
            float2 U3t[4] = { make_float2(u3a.x, u3a.y), make_float2(u3a.z, u3a.w),
                              make_float2(u3b.x, u3b.y), make_float2(u3b.z, u3b.w) };
            float2 U4t[4] = { make_float2(u4a.x, u4a.y), make_float2(u4a.z, u4a.w),
                              make_float2(u4b.x, u4b.y), make_float2(u4b.z, u4b.w) };
            float2 G0 = cmulc(U4t[l2], U4t[l3]);                  // jn -> j
            float2 G1 = cmulc(U4t[2 | l2], U4t[2 | l3]);
            roundC(E, G0, G1);
            roundB(E, U3t[l0], U3t[2 | l0], U3t[l1], U3t[2 | l1]);// b3,bp3 -> a3,ap3
            roundA(E, U2t[0], U2t[2], U2t[1], U2t[3]);            // b2,bp2 -> a2,ap2
            roundW(E, w0, w1);                                    // b1,bp1 -> a1,ap1
            Rsm[q][0][lane] = make_float4(E.e00.x, E.e00.y, E.e01.x, E.e01.y);
            Rsm[q][1][lane] = make_float4(E.e10.x, E.e10.y, E.e11.x, E.e11.y);
        }
    }

    __syncthreads();

    // ---------- Z_q = sum over env (sign = (-1)^{lane bit 4}) ----------
    {
        int qz = tid >> 2, part = tid & 3;
        float acc = 0.f;
        #pragma unroll
        for (int i = 0; i < 8; ++i) {
            int ln = part * 8 + i;
            float4 la = Lsm[qz + 1][0][ln], ra = Rsm[qz + 1][0][ln];
            float4 lb = Lsm[qz + 1][1][ln], rb = Rsm[qz + 1][1][ln];
            float s = la.x * ra.x - la.y * ra.y + la.z * ra.z - la.w * ra.w
                    + lb.x * rb.x - lb.y * rb.y + lb.z * rb.z - lb.w * rb.w;
            acc += (ln & 16) ? -s : s;
        }
        acc += __shfl_xor_sync(0xffffffffu, acc, 1);
        acc += __shfl_xor_sync(0xffffffffu, acc, 2);
        if (part == 0) out[(size_t)bat * 16 + qz] = acc;
    }
}

extern "C" void kernel_launch(void* const* d_in, const int* in_sizes, int n_in,
                              void* d_out, int out_size) {
    const float* ctx = nullptr;
    const float* Wm  = nullptr;
    const float* bv  = nullptr;
    const float* prm = nullptr;
    for (int i = 0; i < n_in; ++i) {
        int sz = in_sizes[i];
        const float* p = (const float*)d_in[i];
        if (sz == 16)        bv  = p;
        else if (sz == 192)  prm = p;
        else if (sz == 4096) Wm  = p;
        else                 ctx = p;  // B*256
    }
    if (!ctx) ctx = (const float*)d_in[0];
    if (!Wm)  Wm  = (const float*)d_in[1];
    if (!bv)  bv  = (const float*)d_in[2];
    if (!prm) prm = (const float*)d_in[3];

    float* out = (float*)d_out;
    int B = out_size / 16;
    if (B <= 0) return;
    pqc_mps_kernel<<<B, 64>>>(ctx, Wm, bv, prm, out);
}

// round 14
// speedup vs baseline: 1.3384x; 1.3384x over previous
#include <cuda_runtime.h>
#include <cuda_bf16.h>
#include <cstddef>

// ============================================================================
// MiniQuixerPQCBlock — exact MPS (bond dim 16), warp-register environments.
// R13: ONE warp per batch runs BOTH sweeps interleaved (2 independent
// dependency chains per warp -> ILP-based latency hiding at low occupancy).
// R11 pass structure (5 single-bit lane passes + 2 in-thread passes per site).
// No block barriers anywhere; block = 32 threads.
// ============================================================================

__device__ __forceinline__ float2 cmul(float2 a, float2 b) {
    return make_float2(fmaf(a.x, b.x, -a.y * b.y), fmaf(a.x, b.y, a.y * b.x));
}
__device__ __forceinline__ float2 cfma(float2 a, float2 b, float2 c) {      // c += a*b
    c.x = fmaf(a.x, b.x, fmaf(-a.y, b.y, c.x));
    c.y = fmaf(a.x, b.y, fmaf(a.y, b.x, c.y));
    return c;
}
__device__ __forceinline__ float2 cmulc(float2 a, float2 b) {               // a*conj(b)
    return make_float2(fmaf(a.x, b.x, a.y * b.y), fmaf(a.y, b.x, -a.x * b.y));
}
__device__ __forceinline__ float2 cfmac(float2 a, float2 b, float2 c) {     // c += a*conj(b)
    c.x = fmaf(a.x, b.x, fmaf(a.y, b.y, c.x));
    c.y = fmaf(a.y, b.x, fmaf(-a.x, b.y, c.y));
    return c;
}
__device__ __forceinline__ float2 shflx(float2 v, int m) {
    v.x = __shfl_xor_sync(0xffffffffu, v.x, m);
    v.y = __shfl_xor_sync(0xffffffffu, v.y, m);
    return v;
}

struct Env { float2 e00, e01, e10, e11; };  // e[r1][r0]

__device__ __forceinline__ Env shfl_env(const Env& E, int m) {
    Env P;
    P.e00 = shflx(E.e00, m); P.e01 = shflx(E.e01, m);
    P.e10 = shflx(E.e10, m); P.e11 = shflx(E.e11, m);
    return P;
}
// in-thread XOR pass over r0 (ket)
__device__ __forceinline__ void pass_w_ket(Env& E, float2 w0, float2 w1) {
    float2 n00 = cfma(w1, E.e01, cmul(w0, E.e00));
    float2 n01 = cfma(w0, E.e01, cmul(w1, E.e00));
    float2 n10 = cfma(w1, E.e11, cmul(w0, E.e10));
    float2 n11 = cfma(w0, E.e11, cmul(w1, E.e10));
    E.e00 = n00; E.e01 = n01; E.e10 = n10; E.e11 = n11;
}
// in-thread conj pass over r1 (bra)
__device__ __forceinline__ void pass_w_bra(Env& E, float2 w0, float2 w1) {
    float2 n00 = cfmac(E.e10, w1, cmulc(E.e00, w0));
    float2 n10 = cfmac(E.e10, w0, cmulc(E.e00, w1));
    float2 n01 = cfmac(E.e11, w1, cmulc(E.e01, w0));
    float2 n11 = cfmac(E.e11, w0, cmulc(E.e01, w1));
    E.e00 = n00; E.e01 = n01; E.e10 = n10; E.e11 = n11;
}
// lane pass, plain gates selected per r0 column (U2 ket)
__device__ __forceinline__ void pass_lane_ket_r0(Env& E, int m,
        float2 a0, float2 b0, float2 a1, float2 b1) {
    Env P = shfl_env(E, m);
    E.e00 = cfma(b0, P.e00, cmul(a0, E.e00));
    E.e10 = cfma(b0, P.e10, cmul(a0, E.e10));
    E.e01 = cfma(b1, P.e01, cmul(a1, E.e01));
    E.e11 = cfma(b1, P.e11, cmul(a1, E.e11));
}
// lane pass, conj gates per r1 row (U2 bra)
__device__ __forceinline__ void pass_lane_bra_r1(Env& E, int m,
        float2 a0, float2 b0, float2 a1, float2 b1) {
    Env P = shfl_env(E, m);
    E.e00 = cfmac(P.e00, b0, cmulc(E.e00, a0));
    E.e01 = cfmac(P.e01, b0, cmulc(E.e01, a0));
    E.e10 = cfmac(P.e10, b1, cmulc(E.e10, a1));
    E.e11 = cfmac(P.e11, b1, cmulc(E.e11, a1));
}
// lane pass, plain uniform gates
__device__ __forceinline__ void pass_lane_ket_uni(Env& E, int m, float2 gA, float2 gB) {
    Env P = shfl_env(E, m);
    E.e00 = cfma(gB, P.e00, cmul(gA, E.e00));
    E.e01 = cfma(gB, P.e01, cmul(gA, E.e01));
    E.e10 = cfma(gB, P.e10, cmul(gA, E.e10));
    E.e11 = cfma(gB, P.e11, cmul(gA, E.e11));
}
// lane pass, conj uniform gates
__device__ __forceinline__ void pass_lane_bra_uni(Env& E, int m, float2 gA, float2 gB) {
    Env P = shfl_env(E, m);
    E.e00 = cfmac(P.e00, gB, cmulc(E.e00, gA));
    E.e01 = cfmac(P.e01, gB, cmulc(E.e01, gA));
    E.e10 = cfmac(P.e10, gB, cmulc(E.e10, gA));
    E.e11 = cfmac(P.e11, gB, cmulc(E.e11, gA));
}

__global__ __launch_bounds__(32) void pqc_mps_kernel(
    const float* __restrict__ ctx,   // [B, 256]
    const float* __restrict__ Wm,    // [16, 256]
    const float* __restrict__ bv,    // [16]
    const float* __restrict__ prm,   // [4, 16, 3]
    float* __restrict__ out)         // [B, 16]
{
    __shared__ __align__(16) float4 Lsm[17][2][33];  // padded: q-slab 66 f4 (bank spread)
    __shared__ __align__(16) float4 Rsm[17][2][33];
    __shared__ __align__(16) float2 Usm[4][16][4];   // fused gates [layer][wire][d*2+c]
    __shared__ __align__(16) float2 wsm[16][2];      // U1 * RX(angle)|0>

    const int lane = threadIdx.x;
    const int bat  = blockIdx.x;

    // ---------- fused variational gates U = RZ*RY*RX (2 per thread) ----------
    #pragma unroll
    for (int rep = 0; rep < 2; ++rep) {
        int idx = lane + rep * 32;
        int l = idx >> 4, q = idx & 15;
        const float* p = prm + (size_t)(l * 16 + q) * 3;
        float ca = cosf(0.5f * p[0]), sa = sinf(0.5f * p[0]);
        float cb = cosf(0.5f * p[1]), sb = sinf(0.5f * p[1]);
        float cg = cosf(0.5f * p[2]), sg = sinf(0.5f * p[2]);
        float2 X00 = make_float2(ca, 0.f), X01 = make_float2(0.f, -sa);
        float2 M00 = make_float2(cb * X00.x - sb * X01.x, cb * X00.y - sb * X01.y);
        float2 M01 = make_float2(cb * X01.x - sb * X00.x, cb * X01.y - sb * X00.y);
        float2 M10 = make_float2(sb * X00.x + cb * X01.x, sb * X00.y + cb * X01.y);
        float2 M11 = make_float2(sb * X01.x + cb * X00.x, sb * X01.y + cb * X00.y);
        float2 em = make_float2(cg, -sg), ep = make_float2(cg, sg);
        Usm[l][q][0] = cmul(em, M00);
        Usm[l][q][1] = cmul(em, M01);
        Usm[l][q][2] = cmul(ep, M10);
        Usm[l][q][3] = cmul(ep, M11);
    }
    // ---------- encoding dots: q = lane>>1, half row each ----------
    float dot;
    {
        int q = lane >> 1, half = lane & 1;
        const float4* cr = (const float4*)(ctx + (size_t)bat * 256) + half * 32;
        const float4* wr = (const float4*)(Wm + (size_t)q * 256) + half * 32;
        float acc = 0.f;
        #pragma unroll
        for (int k = 0; k < 32; ++k) {
            float4 c = cr[k], w = wr[k];
            acc = fmaf(c.x, w.x, acc); acc = fmaf(c.y, w.y, acc);
            acc = fmaf(c.z, w.z, acc); acc = fmaf(c.w, w.w, acc);
        }
        acc += __shfl_xor_sync(0xffffffffu, acc, 1);
        dot = acc;  // valid in both halves of each pair
    }
    __syncwarp();
    // ---------- encoding vector folded with layer-1 gate ----------
    {
        // lane q (q<16) needs dot of qubit q, held by lanes 2q/2q+1
        float dq = __shfl_sync(0xffffffffu, dot, (lane & 15) * 2);
        if (lane < 16) {
            float ang = 3.14159265358979323846f * tanhf(dq + bv[lane]);
            float h = 0.5f * ang;
            float2 v0 = make_float2(cosf(h), 0.f);
            float2 v1 = make_float2(0.f, -sinf(h));
            wsm[lane][0] = cfma(Usm[0][lane][1], v1, cmul(Usm[0][lane][0], v0));
            wsm[lane][1] = cfma(Usm[0][lane][3], v1, cmul(Usm[0][lane][2], v0));
        }
    }
    __syncwarp();

    const int l0 = lane & 1, l1 = (lane >> 1) & 1;
    const int l2 = (lane >> 2) & 1, l3 = (lane >> 3) & 1;

    // ---------- both sweeps, interleaved, in one warp ----------
    Env EL, ER;
    {
        float2 z = make_float2(0.f, 0.f);
        EL.e00 = make_float2(lane == 0 ? 1.f : 0.f, 0.f);
        EL.e01 = z; EL.e10 = z; EL.e11 = z;
        float2 one = make_float2(1.f, 0.f);
        ER.e00 = one; ER.e01 = one; ER.e10 = one; ER.e11 = one;
        Rsm[16][0][lane] = make_float4(1.f, 0.f, 1.f, 0.f);
        Rsm[16][1][lane] = make_float4(1.f, 0.f, 1.f, 0.f);
    }

    #pragma unroll 1
    for (int i = 0; i < 16; ++i) {
        const int qL = i;        // left site index
        const int qR = 15 - i;   // right site index (valid while >= 1)
        const bool doR = (qR >= 1);

        // left gates
        float2 wL0 = wsm[qL][0], wL1 = wsm[qL][1];
        const float2* U2L = Usm[1][qL];
        const float2* U3L = Usm[2][qL];
        const float2* U4L = Usm[3][qL];
        // right gates
        float2 wR0 = wsm[qR][0], wR1 = wsm[qR][1];
        const float2* U2R = Usm[1][qR];
        const float2* U3R = Usm[2][qR];
        const float2* U4R = Usm[3][qR];

        // interleave the two independent chains pass-by-pass
        float2 GR0 = cmulc(U4R[l2], U4R[l3]);
        float2 GR1 = cmulc(U4R[2 | l2], U4R[2 | l3]);
        pass_w_ket(EL, wL0, wL1);
        if (doR) pass_lane_ket_uni(ER, 16, GR0, GR1);
        pass_w_bra(EL, wL0, wL1);
        if (doR) pass_lane_ket_uni(ER, 4, U3R[l0], U3R[2 | l0]);
        pass_lane_ket_r0(EL, 1, U2L[0], U2L[2], U2L[1], U2L[3]);
        if (doR) pass_lane_bra_uni(ER, 8, U3R[l1], U3R[2 | l1]);
        pass_lane_bra_r1(EL, 2, U2L[0], U2L[2], U2L[1], U2L[3]);
        if (doR) pass_lane_ket_r0(ER, 1, U2R[0], U2R[2], U2R[1], U2R[3]);
        pass_lane_ket_uni(EL, 4, U3L[l0], U3L[2 | l0]);
        if (doR) pass_lane_bra_r1(ER, 2, U2R[0], U2R[2], U2R[1], U2R[3]);
        pass_lane_bra_uni(EL, 8, U3L[l1], U3L[2 | l1]);
        if (doR) pass_w_ket(ER, wR0, wR1);
        float2 GL0 = cmulc(U4L[l2], U4L[l3]);
        float2 GL1 = cmulc(U4L[2 | l2], U4L[2 | l3]);
        pass_lane_ket_uni(EL, 16, GL0, GL1);
        if (doR) pass_w_bra(ER, wR0, wR1);

        Lsm[qL + 1][0][lane] = make_float4(EL.e00.x, EL.e00.y, EL.e01.x, EL.e01.y);
        Lsm[qL + 1][1][lane] = make_float4(EL.e10.x, EL.e10.y, EL.e11.x, EL.e11.y);
        if (doR) {
            Rsm[qR][0][lane] = make_float4(ER.e00.x, ER.e00.y, ER.e01.x, ER.e01.y);
            Rsm[qR][1][lane] = make_float4(ER.e10.x, ER.e10.y, ER.e11.x, ER.e11.y);
        }
    }
    __syncwarp();

    // ---------- Z_q = sum over env (sign = (-1)^{lane bit 4}) ----------
    {
        int qz = lane >> 1, half = lane & 1;
        float acc = 0.f;
        #pragma unroll
        for (int i = 0; i < 16; ++i) {
            int ln = 2 * i + half;
            float4 la = Lsm[qz + 1][0][ln], ra = Rsm[qz + 1][0][ln];
            float4 lb = Lsm[qz + 1][1][ln], rb = Rsm[qz + 1][1][ln];
            float s = la.x * ra.x - la.y * ra.y + la.z * ra.z - la.w * ra.w
                    + lb.x * rb.x - lb.y * rb.y + lb.z * rb.z - lb.w * rb.w;
            acc += (ln & 16) ? -s : s;
        }
        acc += __shfl_xor_sync(0xffffffffu, acc, 1);
        if (half == 0) out[(size_t)bat * 16 + qz] = acc;
    }
}

extern "C" void kernel_launch(void* const* d_in, const int* in_sizes, int n_in,
                              void* d_out, int out_size) {
    const float* ctx = nullptr;
    const float* Wm  = nullptr;
    const float* bv  = nullptr;
    const float* prm = nullptr;
    for (int i = 0; i < n_in; ++i) {
        int sz = in_sizes[i];
        const float* p = (const float*)d_in[i];
        if (sz == 16)        bv  = p;
        else if (sz == 192)  prm = p;
        else if (sz == 4096) Wm  = p;
        else                 ctx = p;  // B*256
    }
    if (!ctx) ctx = (const float*)d_in[0];
    if (!Wm)  Wm  = (const float*)d_in[1];
    if (!bv)  bv  = (const float*)d_in[2];
    if (!prm) prm = (const float*)d_in[3];

    float* out = (float*)d_out;
    int B = out_size / 16;
    if (B <= 0) return;
    pqc_mps_kernel<<<B, 32>>>(ctx, Wm, bv, prm, out);
}

// round 15
// speedup vs baseline: 1.4757x; 1.1026x over previous
#include <cuda_runtime.h>
#include <cuda_bf16.h>
#include <cstddef>

// ============================================================================
// MiniQuixerPQCBlock — exact MPS (bond dim 16), warp-register environments.
// R14: R13 structure (one warp per batch, L/R chains interleaved) with the
// environment packed along the bra bit as f32x2 pairs; every pass is 16
// packed fma.rn.f32x2 (FFMA2) — ~half the FMA-pipe issue slots of R13.
// ============================================================================

typedef unsigned long long u64;

__device__ __forceinline__ u64 pk2(float lo, float hi) {
    u64 r; asm("mov.b64 %0, {%1, %2};" : "=l"(r) : "f"(lo), "f"(hi)); return r;
}
__device__ __forceinline__ u64 spl(float v) { return pk2(v, v); }
__device__ __forceinline__ float2 up2(u64 v) {
    float2 r; asm("mov.b64 {%0, %1}, %2;" : "=f"(r.x), "=f"(r.y) : "l"(v)); return r;
}
__device__ __forceinline__ u64 swp(u64 v) {           // swap lo/hi halves
    float2 t = up2(v); return pk2(t.y, t.x);
}
__device__ __forceinline__ u64 ffma2(u64 a, u64 b, u64 c) {
    u64 r; asm("fma.rn.f32x2 %0, %1, %2, %3;" : "=l"(r) : "l"(a), "l"(b), "l"(c)); return r;
}
__device__ __forceinline__ u64 fmul2(u64 a, u64 b) {
    u64 r; asm("mul.rn.f32x2 %0, %1, %2;" : "=l"(r) : "l"(a), "l"(b)); return r;
}
__device__ __forceinline__ u64 shfl64(u64 v, int m) {
    return __shfl_xor_sync(0xffffffffu, v, m);
}
__device__ __forceinline__ float2 cmul(float2 a, float2 b) {
    return make_float2(fmaf(a.x, b.x, -a.y * b.y), fmaf(a.x, b.y, a.y * b.x));
}
__device__ __forceinline__ float2 cfma(float2 a, float2 b, float2 c) {
    c.x = fmaf(a.x, b.x, fmaf(-a.y, b.y, c.x));
    c.y = fmaf(a.x, b.y, fmaf(a.y, b.x, c.y));
    return c;
}
__device__ __forceinline__ float2 cmulc(float2 a, float2 b) {  // a*conj(b)
    return make_float2(fmaf(a.x, b.x, a.y * b.y), fmaf(a.y, b.x, -a.x * b.y));
}

// Packed environment: packs along bra bit r1.
// R0={re e00, re e10}, I0={im e00, im e10} (r0=0);  R1,I1 same for r0=1.
struct PEnv { u64 R0, I0, R1, I1; };

// in-thread ket pass over r0 (plain gates w0 self, w1 partner-column)
__device__ __forceinline__ void pket_in(PEnv& E, float2 w0, float2 w1) {
    u64 w0x = spl(w0.x), w0y = spl(w0.y), w0yn = spl(-w0.y);
    u64 w1x = spl(w1.x), w1y = spl(w1.y), w1yn = spl(-w1.y);
    u64 nR0 = ffma2(E.I1, w1yn, ffma2(E.R1, w1x, ffma2(E.I0, w0yn, fmul2(E.R0, w0x))));
    u64 nI0 = ffma2(E.R1, w1y,  ffma2(E.I1, w1x, ffma2(E.R0, w0y,  fmul2(E.I0, w0x))));
    u64 nR1 = ffma2(E.I1, w0yn, ffma2(E.R1, w0x, ffma2(E.I0, w1yn, fmul2(E.R0, w1x))));
    u64 nI1 = ffma2(E.R1, w0y,  ffma2(E.I1, w0x, ffma2(E.R0, w1y,  fmul2(E.I0, w1x))));
    E.R0 = nR0; E.I0 = nI0; E.R1 = nR1; E.I1 = nI1;
}
// in-thread bra pass over r1 (conj gates; mixes lo/hi within packs via swap)
__device__ __forceinline__ void pbra_in(PEnv& E, float2 w0, float2 w1) {
    u64 w0x = spl(w0.x), w0y = spl(w0.y), w0yn = spl(-w0.y);
    u64 w1x = spl(w1.x), w1y = spl(w1.y), w1yn = spl(-w1.y);
    u64 sR0 = swp(E.R0), sI0 = swp(E.I0), sR1 = swp(E.R1), sI1 = swp(E.I1);
    u64 nR0 = ffma2(sI0, w1y,  ffma2(sR0, w1x, ffma2(E.I0, w0y,  fmul2(E.R0, w0x))));
    u64 nI0 = ffma2(sR0, w1yn, ffma2(sI0, w1x, ffma2(E.R0, w0yn, fmul2(E.I0, w0x))));
    u64 nR1 = ffma2(sI1, w1y,  ffma2(sR1, w1x, ffma2(E.I1, w0y,  fmul2(E.R1, w0x))));
    u64 nI1 = ffma2(sR1, w1yn, ffma2(sI1, w1x, ffma2(E.R1, w0yn, fmul2(E.I1, w0x))));
    E.R0 = nR0; E.I0 = nI0; E.R1 = nR1; E.I1 = nI1;
}
// lane ket pass, gates per pack (r0): pack0 uses (a0,b0), pack1 uses (a1,b1)
__device__ __forceinline__ void pket_lane2(PEnv& E, int m,
        float2 a0, float2 b0, float2 a1, float2 b1) {
    u64 Rp0 = shfl64(E.R0, m), Ip0 = shfl64(E.I0, m);
    u64 Rp1 = shfl64(E.R1, m), Ip1 = shfl64(E.I1, m);
    u64 a0x = spl(a0.x), a0y = spl(a0.y), a0yn = spl(-a0.y);
    u64 b0x = spl(b0.x), b0y = spl(b0.y), b0yn = spl(-b0.y);
    u64 a1x = spl(a1.x), a1y = spl(a1.y), a1yn = spl(-a1.y);
    u64 b1x = spl(b1.x), b1y = spl(b1.y), b1yn = spl(-b1.y);
    E.R0 = ffma2(Ip0, b0yn, ffma2(Rp0, b0x, ffma2(E.I0, a0yn, fmul2(E.R0, a0x))));
    u64 nI0 = ffma2(Rp0, b0y, ffma2(Ip0, b0x, ffma2(E.R0 /*dummy*/, spl(0.f), fmul2(E.I0, a0x))));
    // NOTE: nI0 must use OLD R0 — recompute properly below.
    (void)nI0;
    // (structured version below)
    E.R0 = E.R0; // placeholder, real implementation in pket_lane2_impl
}

// --- correct structured lane passes (old values captured first) ---
__device__ __forceinline__ void pket_lane(PEnv& E, int m,
        float2 a0, float2 b0, float2 a1, float2 b1) {
    u64 Rp0 = shfl64(E.R0, m), Ip0 = shfl64(E.I0, m);
    u64 Rp1 = shfl64(E.R1, m), Ip1 = shfl64(E.I1, m);
    u64 a0x = spl(a0.x), a0y = spl(a0.y), a0yn = spl(-a0.y);
    u64 b0x = spl(b0.x), b0y = spl(b0.y), b0yn = spl(-b0.y);
    u64 a1x = spl(a1.x), a1y = spl(a1.y), a1yn = spl(-a1.y);
    u64 b1x = spl(b1.x), b1y = spl(b1.y), b1yn = spl(-b1.y);
    u64 nR0 = ffma2(Ip0, b0yn, ffma2(Rp0, b0x, ffma2(E.I0, a0yn, fmul2(E.R0, a0x))));
    u64 nI0 = ffma2(Rp0, b0y,  ffma2(Ip0, b0x, ffma2(E.R0, a0y,  fmul2(E.I0, a0x))));
    u64 nR1 = ffma2(Ip1, b1yn, ffma2(Rp1, b1x, ffma2(E.I1, a1yn, fmul2(E.R1, a1x))));
    u64 nI1 = ffma2(Rp1, b1y,  ffma2(Ip1, b1x, ffma2(E.R1, a1y,  fmul2(E.I1, a1x))));
    E.R0 = nR0; E.I0 = nI0; E.R1 = nR1; E.I1 = nI1;
}
// lane bra pass, gates per slot (r1): lo slot (a0,b0), hi slot (a1,b1), conj
__device__ __forceinline__ void pbra_lane(PEnv& E, int m,
        float2 a0, float2 b0, float2 a1, float2 b1) {
    u64 Rp0 = shfl64(E.R0, m), Ip0 = shfl64(E.I0, m);
    u64 Rp1 = shfl64(E.R1, m), Ip1 = shfl64(E.I1, m);
    u64 AX = pk2(a0.x, a1.x), AY = pk2(a0.y, a1.y), AYn = pk2(-a0.y, -a1.y);
    u64 BX = pk2(b0.x, b1.x), BY = pk2(b0.y, b1.y), BYn = pk2(-b0.y, -b1.y);
    u64 nR0 = ffma2(Ip0, BY,  ffma2(Rp0, BX, ffma2(E.I0, AY,  fmul2(E.R0, AX))));
    u64 nI0 = ffma2(Rp0, BYn, ffma2(Ip0, BX, ffma2(E.R0, AYn, fmul2(E.I0, AX))));
    u64 nR1 = ffma2(Ip1, BY,  ffma2(Rp1, BX, ffma2(E.I1, AY,  fmul2(E.R1, AX))));
    u64 nI1 = ffma2(Rp1, BYn, ffma2(Ip1, BX, ffma2(E.R1, AYn, fmul2(E.I1, AX))));
    E.R0 = nR0; E.I0 = nI0; E.R1 = nR1; E.I1 = nI1;
}

__global__ __launch_bounds__(32) void pqc_mps_kernel(
    const float* __restrict__ ctx,   // [B, 256]
    const float* __restrict__ Wm,    // [16, 256]
    const float* __restrict__ bv,    // [16]
    const float* __restrict__ prm,   // [4, 16, 3]
    float* __restrict__ out)         // [B, 16]
{
    __shared__ __align__(16) float4 Lsm[17][2][33];
    __shared__ __align__(16) float4 Rsm[17][2][33];
    __shared__ __align__(16) float2 Usm[4][16][4];
    __shared__ __align__(16) float2 wsm[16][2];

    const int lane = threadIdx.x;
    const int bat  = blockIdx.x;

    // ---------- fused variational gates (2 per thread) ----------
    #pragma unroll
    for (int rep = 0; rep < 2; ++rep) {
        int idx = lane + rep * 32;
        int l = idx >> 4, q = idx & 15;
        const float* p = prm + (size_t)(l * 16 + q) * 3;
        float ca = cosf(0.5f * p[0]), sa = sinf(0.5f * p[0]);
        float cb = cosf(0.5f * p[1]), sb = sinf(0.5f * p[1]);
        float cg = cosf(0.5f * p[2]), sg = sinf(0.5f * p[2]);
        float2 X00 = make_float2(ca, 0.f), X01 = make_float2(0.f, -sa);
        float2 M00 = make_float2(cb * X00.x - sb * X01.x, cb * X00.y - sb * X01.y);
        float2 M01 = make_float2(cb * X01.x - sb * X00.x, cb * X01.y - sb * X00.y);
        float2 M10 = make_float2(sb * X00.x + cb * X01.x, sb * X00.y + cb * X01.y);
        float2 M11 = make_float2(sb * X01.x + cb * X00.x, sb * X01.y + cb * X00.y);
        float2 em = make_float2(cg, -sg), ep = make_float2(cg, sg);
        Usm[l][q][0] = cmul(em, M00);
        Usm[l][q][1] = cmul(em, M01);
        Usm[l][q][2] = cmul(ep, M10);
        Usm[l][q][3] = cmul(ep, M11);
    }
    // ---------- encoding dots ----------
    float dot;
    {
        int q = lane >> 1, half = lane & 1;
        const float4* cr = (const float4*)(ctx + (size_t)bat * 256) + half * 32;
        const float4* wr = (const float4*)(Wm + (size_t)q * 256) + half * 32;
        float acc = 0.f;
        #pragma unroll
        for (int k = 0; k < 32; ++k) {
            float4 c = cr[k], w = wr[k];
            acc = fmaf(c.x, w.x, acc); acc = fmaf(c.y, w.y, acc);
            acc = fmaf(c.z, w.z, acc); acc = fmaf(c.w, w.w, acc);
        }
        acc += __shfl_xor_sync(0xffffffffu, acc, 1);
        dot = acc;
    }
    __syncwarp();
    {
        float dq = __shfl_sync(0xffffffffu, dot, (lane & 15) * 2);
        if (lane < 16) {
            float ang = 3.14159265358979323846f * tanhf(dq + bv[lane]);
            float h = 0.5f * ang;
            float2 v0 = make_float2(cosf(h), 0.f);
            float2 v1 = make_float2(0.f, -sinf(h));
            wsm[lane][0] = cfma(Usm[0][lane][1], v1, cmul(Usm[0][lane][0], v0));
            wsm[lane][1] = cfma(Usm[0][lane][3], v1, cmul(Usm[0][lane][2], v0));
        }
    }
    __syncwarp();

    const int l0 = lane & 1, l1 = (lane >> 1) & 1;
    const int l2 = (lane >> 2) & 1, l3 = (lane >> 3) & 1;

    PEnv EL, ER;
    EL.R0 = pk2(lane == 0 ? 1.f : 0.f, 0.f);
    EL.I0 = 0; EL.R1 = 0; EL.I1 = 0;
    ER.R0 = pk2(1.f, 1.f); ER.R1 = pk2(1.f, 1.f); ER.I0 = 0; ER.I1 = 0;
    Rsm[16][0][lane] = make_float4(1.f, 0.f, 1.f, 0.f);
    Rsm[16][1][lane] = make_float4(1.f, 0.f, 1.f, 0.f);

    // one site-transfer of a chain, given gate tables
    #define SITE_L(qq)                                                         \
        {                                                                      \
            float2 w0 = wsm[qq][0], w1 = wsm[qq][1];                           \
            const float2* U2 = Usm[1][qq];                                     \
            const float2* U3 = Usm[2][qq];                                     \
            const float2* U4 = Usm[3][qq];                                     \
            pket_in(EL, w0, w1);                                               \
            pbra_in(EL, w0, w1);                                               \
            pket_lane(EL, 1, U2[0], U2[2], U2[1], U2[3]);                      \
            pbra_lane(EL, 2, U2[0], U2[2], U2[1], U2[3]);                      \
            pket_lane(EL, 4, U3[l0], U3[2 | l0], U3[l0], U3[2 | l0]);          \
            pbra_lane(EL, 8, U3[l1], U3[2 | l1], U3[l1], U3[2 | l1]);          \
            float2 G0 = cmulc(U4[l2], U4[l3]);                                 \
            float2 G1 = cmulc(U4[2 | l2], U4[2 | l3]);                         \
            pket_lane(EL, 16, G0, G1, G0, G1);                                 \
            float2 r0 = up2(EL.R0), i0 = up2(EL.I0);                           \
            float2 r1 = up2(EL.R1), i1 = up2(EL.I1);                           \
            Lsm[(qq) + 1][0][lane] = make_float4(r0.x, i0.x, r1.x, i1.x);      \
            Lsm[(qq) + 1][1][lane] = make_float4(r0.y, i0.y, r1.y, i1.y);      \
        }

    #pragma unroll 1
    for (int i = 0; i < 15; ++i) {
        const int qL = i, qR = 15 - i;
        float2 wL0 = wsm[qL][0], wL1 = wsm[qL][1];
        const float2* U2L = Usm[1][qL];
        const float2* U3L = Usm[2][qL];
        const float2* U4L = Usm[3][qL];
        float2 wR0 = wsm[qR][0], wR1 = wsm[qR][1];
        const float2* U2R = Usm[1][qR];
        const float2* U3R = Usm[2][qR];
        const float2* U4R = Usm[3][qR];

        // interleave the two independent chains pass-by-pass
        float2 GR0 = cmulc(U4R[l2], U4R[l3]);
        float2 GR1 = cmulc(U4R[2 | l2], U4R[2 | l3]);
        pket_in(EL, wL0, wL1);
        pket_lane(ER, 16, GR0, GR1, GR0, GR1);
        pbra_in(EL, wL0, wL1);
        pket_lane(ER, 4, U3R[l0], U3R[2 | l0], U3R[l0], U3R[2 | l0]);
        pket_lane(EL, 1, U2L[0], U2L[2], U2L[1], U2L[3]);
        pbra_lane(ER, 8, U3R[l1], U3R[2 | l1], U3R[l1], U3R[2 | l1]);
        pbra_lane(EL, 2, U2L[0], U2L[2], U2L[1], U2L[3]);
        pket_lane(ER, 1, U2R[0], U2R[2], U2R[1], U2R[3]);
        pket_lane(EL, 4, U3L[l0], U3L[2 | l0], U3L[l0], U3L[2 | l0]);
        pbra_lane(ER, 2, U2R[0], U2R[2], U2R[1], U2R[3]);
        pbra_lane(EL, 8, U3L[l1], U3L[2 | l1], U3L[l1], U3L[2 | l1]);
        pket_in(ER, wR0, wR1);
        float2 GL0 = cmulc(U4L[l2], U4L[l3]);
        float2 GL1 = cmulc(U4L[2 | l2], U4L[2 | l3]);
        pket_lane(EL, 16, GL0, GL1, GL0, GL1);
        pbra_in(ER, wR0, wR1);

        {
            float2 r0 = up2(EL.R0), i0 = up2(EL.I0);
            float2 r1 = up2(EL.R1), i1 = up2(EL.I1);
            Lsm[qL + 1][0][lane] = make_float4(r0.x, i0.x, r1.x, i1.x);
            Lsm[qL + 1][1][lane] = make_float4(r0.y, i0.y, r1.y, i1.y);
            r0 = up2(ER.R0); i0 = up2(ER.I0);
            r1 = up2(ER.R1); i1 = up2(ER.I1);
            Rsm[qR][0][lane] = make_float4(r0.x, i0.x, r1.x, i1.x);
            Rsm[qR][1][lane] = make_float4(r0.y, i0.y, r1.y, i1.y);
        }
    }
    SITE_L(15);
    __syncwarp();

    // ---------- Z_q ----------
    {
        int qz = lane >> 1, half = lane & 1;
        float acc = 0.f;
        #pragma unroll
        for (int i = 0; i < 16; ++i) {
            int ln = 2 * i + half;
            float4 la = Lsm[qz + 1][0][ln], ra = Rsm[qz + 1][0][ln];
            float4 lb = Lsm[qz + 1][1][ln], rb = Rsm[qz + 1][1][ln];
            float s = la.x * ra.x - la.y * ra.y + la.z * ra.z - la.w * ra.w
                    + lb.x * rb.x - lb.y * rb.y + lb.z * rb.z - lb.w * rb.w;
            acc += (ln & 16) ? -s : s;
        }
        acc += __shfl_xor_sync(0xffffffffu, acc, 1);
        if (half == 0) out[(size_t)bat * 16 + qz] = acc;
    }
}

extern "C" void kernel_launch(void* const* d_in, const int* in_sizes, int n_in,
                              void* d_out, int out_size) {
    const float* ctx = nullptr;
    const float* Wm  = nullptr;
    const float* bv  = nullptr;
    const float* prm = nullptr;
    for (int i = 0; i < n_in; ++i) {
        int sz = in_sizes[i];
        const float* p = (const float*)d_in[i];
        if (sz == 16)        bv  = p;
        else if (sz == 192)  prm = p;
        else if (sz == 4096) Wm  = p;
        else                 ctx = p;  // B*256
    }
    if (!ctx) ctx = (const float*)d_in[0];
    if (!Wm)  Wm  = (const float*)d_in[1];
    if (!bv)  bv  = (const float*)d_in[2];
    if (!prm) prm = (const float*)d_in[3];

    float* out = (float*)d_out;
    int B = out_size / 16;
    if (B <= 0) return;
    pqc_mps_kernel<<<B, 32>>>(ctx, Wm, bv, prm, out);
}

// round 16
// speedup vs baseline: 1.4981x; 1.0152x over previous
#include <cuda_runtime.h>
#include <cuda_bf16.h>
#include <cstddef>

// ============================================================================
// MiniQuixerPQCBlock — exact MPS (bond dim 16), warp-register environments.
// R15: 4 warps per CTA (2 batches x {L,R} chain) so warps cover all 4 SMSPs
// (SMSP = wid%4 — single-warp CTAs stacked everything on SMSP 0).
// Z fused via 15-slot smem history, 1 __syncthreads per site.
// Packed f32x2 passes from R14 unchanged.
// ============================================================================

typedef unsigned long long u64;

__device__ __forceinline__ u64 pk2(float lo, float hi) {
    u64 r; asm("mov.b64 %0, {%1, %2};" : "=l"(r) : "f"(lo), "f"(hi)); return r;
}
__device__ __forceinline__ u64 spl(float v) { return pk2(v, v); }
__device__ __forceinline__ float2 up2(u64 v) {
    float2 r; asm("mov.b64 {%0, %1}, %2;" : "=f"(r.x), "=f"(r.y) : "l"(v)); return r;
}
__device__ __forceinline__ u64 swp(u64 v) { float2 t = up2(v); return pk2(t.y, t.x); }
__device__ __forceinline__ u64 ffma2(u64 a, u64 b, u64 c) {
    u64 r; asm("fma.rn.f32x2 %0, %1, %2, %3;" : "=l"(r) : "l"(a), "l"(b), "l"(c)); return r;
}
__device__ __forceinline__ u64 fmul2(u64 a, u64 b) {
    u64 r; asm("mul.rn.f32x2 %0, %1, %2;" : "=l"(r) : "l"(a), "l"(b)); return r;
}
__device__ __forceinline__ u64 shfl64(u64 v, int m) { return __shfl_xor_sync(0xffffffffu, v, m); }
__device__ __forceinline__ float2 cmul(float2 a, float2 b) {
    return make_float2(fmaf(a.x, b.x, -a.y * b.y), fmaf(a.x, b.y, a.y * b.x));
}
__device__ __forceinline__ float2 cfma(float2 a, float2 b, float2 c) {
    c.x = fmaf(a.x, b.x, fmaf(-a.y, b.y, c.x));
    c.y = fmaf(a.x, b.y, fmaf(a.y, b.x, c.y));
    return c;
}
__device__ __forceinline__ float2 cmulc(float2 a, float2 b) {  // a*conj(b)
    return make_float2(fmaf(a.x, b.x, a.y * b.y), fmaf(a.y, b.x, -a.x * b.y));
}

// Packed env: packs along bra bit r1.
// R0={re e00, re e10}, I0={im e00, im e10} (r0=0); R1,I1 for r0=1.
struct PEnv { u64 R0, I0, R1, I1; };

__device__ __forceinline__ void pket_in(PEnv& E, float2 w0, float2 w1) {
    u64 w0x = spl(w0.x), w0y = spl(w0.y), w0yn = spl(-w0.y);
    u64 w1x = spl(w1.x), w1y = spl(w1.y), w1yn = spl(-w1.y);
    u64 nR0 = ffma2(E.I1, w1yn, ffma2(E.R1, w1x, ffma2(E.I0, w0yn, fmul2(E.R0, w0x))));
    u64 nI0 = ffma2(E.R1, w1y,  ffma2(E.I1, w1x, ffma2(E.R0, w0y,  fmul2(E.I0, w0x))));
    u64 nR1 = ffma2(E.I1, w0yn, ffma2(E.R1, w0x, ffma2(E.I0, w1yn, fmul2(E.R0, w1x))));
    u64 nI1 = ffma2(E.R1, w0y,  ffma2(E.I1, w0x, ffma2(E.R0, w1y,  fmul2(E.I0, w1x))));
    E.R0 = nR0; E.I0 = nI0; E.R1 = nR1; E.I1 = nI1;
}
__device__ __forceinline__ void pbra_in(PEnv& E, float2 w0, float2 w1) {
    u64 w0x = spl(w0.x), w0y = spl(w0.y), w0yn = spl(-w0.y);
    u64 w1x = spl(w1.x), w1y = spl(w1.y), w1yn = spl(-w1.y);
    u64 sR0 = swp(E.R0), sI0 = swp(E.I0), sR1 = swp(E.R1), sI1 = swp(E.I1);
    u64 nR0 = ffma2(sI0, w1y,  ffma2(sR0, w1x, ffma2(E.I0, w0y,  fmul2(E.R0, w0x))));
    u64 nI0 = ffma2(sR0, w1yn, ffma2(sI0, w1x, ffma2(E.R0, w0yn, fmul2(E.I0, w0x))));
    u64 nR1 = ffma2(sI1, w1y,  ffma2(sR1, w1x, ffma2(E.I1, w0y,  fmul2(E.R1, w0x))));
    u64 nI1 = ffma2(sR1, w1yn, ffma2(sI1, w1x, ffma2(E.R1, w0yn, fmul2(E.I1, w0x))));
    E.R0 = nR0; E.I0 = nI0; E.R1 = nR1; E.I1 = nI1;
}
__device__ __forceinline__ void pket_lane(PEnv& E, int m,
        float2 a0, float2 b0, float2 a1, float2 b1) {
    u64 Rp0 = shfl64(E.R0, m), Ip0 = shfl64(E.I0, m);
    u64 Rp1 = shfl64(E.R1, m), Ip1 = shfl64(E.I1, m);
    u64 a0x = spl(a0.x), a0y = spl(a0.y), a0yn = spl(-a0.y);
    u64 b0x = spl(b0.x), b0y = spl(b0.y), b0yn = spl(-b0.y);
    u64 a1x = spl(a1.x), a1y = spl(a1.y), a1yn = spl(-a1.y);
    u64 b1x = spl(b1.x), b1y = spl(b1.y), b1yn = spl(-b1.y);
    u64 nR0 = ffma2(Ip0, b0yn, ffma2(Rp0, b0x, ffma2(E.I0, a0yn, fmul2(E.R0, a0x))));
    u64 nI0 = ffma2(Rp0, b0y,  ffma2(Ip0, b0x, ffma2(E.R0, a0y,  fmul2(E.I0, a0x))));
    u64 nR1 = ffma2(Ip1, b1yn, ffma2(Rp1, b1x, ffma2(E.I1, a1yn, fmul2(E.R1, a1x))));
    u64 nI1 = ffma2(Rp1, b1y,  ffma2(Ip1, b1x, ffma2(E.R1, a1y,  fmul2(E.I1, a1x))));
    E.R0 = nR0; E.I0 = nI0; E.R1 = nR1; E.I1 = nI1;
}
__device__ __forceinline__ void pbra_lane(PEnv& E, int m,
        float2 a0, float2 b0, float2 a1, float2 b1) {
    u64 Rp0 = shfl64(E.R0, m), Ip0 = shfl64(E.I0, m);
    u64 Rp1 = shfl64(E.R1, m), Ip1 = shfl64(E.I1, m);
    u64 AX = pk2(a0.x, a1.x), AY = pk2(a0.y, a1.y), AYn = pk2(-a0.y, -a1.y);
    u64 BX = pk2(b0.x, b1.x), BY = pk2(b0.y, b1.y), BYn = pk2(-b0.y, -b1.y);
    u64 nR0 = ffma2(Ip0, BY,  ffma2(Rp0, BX, ffma2(E.I0, AY,  fmul2(E.R0, AX))));
    u64 nI0 = ffma2(Rp0, BYn, ffma2(Ip0, BX, ffma2(E.R0, AYn, fmul2(E.I0, AX))));
    u64 nR1 = ffma2(Ip1, BY,  ffma2(Rp1, BX, ffma2(E.I1, AY,  fmul2(E.R1, AX))));
    u64 nI1 = ffma2(Rp1, BYn, ffma2(Ip1, BX, ffma2(E.R1, AYn, fmul2(E.I1, AX))));
    E.R0 = nR0; E.I0 = nI0; E.R1 = nR1; E.I1 = nI1;
}

__global__ __launch_bounds__(128) void pqc_mps_kernel(
    const float* __restrict__ ctx,   // [B, 256]
    const float* __restrict__ Wm,    // [16, 256]
    const float* __restrict__ bv,    // [16]
    const float* __restrict__ prm,   // [4, 16, 3]
    float* __restrict__ out,         // [B, 16]
    int B)
{
    // Hist slots 0..6 = L_1..L_7 ; slots 7..14 = R_8..R_15 (slot 7+(j-8) for R_j)
    __shared__ __align__(16) float4 Hist[2][15][2][32];
    __shared__ __align__(16) float2 Usm[4][16][4];   // batch-independent fused gates
    __shared__ __align__(16) float2 wsm[2][16][2];   // per-batch encoding vectors
    __shared__ float pf[2][16];

    const int tid  = threadIdx.x;
    const int lane = tid & 31;
    const int warp = tid >> 5;
    const int wb   = warp >> 1;     // batch within CTA
    const int role = warp & 1;      // 0 = L chain, 1 = R chain
    const int bat  = blockIdx.x * 2 + wb;
    const bool act = (bat < B);

    // ---------- fused variational gates (batch independent) ----------
    if (tid < 64) {
        int l = tid >> 4, q = tid & 15;
        const float* p = prm + (size_t)(l * 16 + q) * 3;
        float ca = cosf(0.5f * p[0]), sa = sinf(0.5f * p[0]);
        float cb = cosf(0.5f * p[1]), sb = sinf(0.5f * p[1]);
        float cg = cosf(0.5f * p[2]), sg = sinf(0.5f * p[2]);
        float2 X00 = make_float2(ca, 0.f), X01 = make_float2(0.f, -sa);
        float2 M00 = make_float2(cb * X00.x - sb * X01.x, cb * X00.y - sb * X01.y);
        float2 M01 = make_float2(cb * X01.x - sb * X00.x, cb * X01.y - sb * X00.y);
        float2 M10 = make_float2(sb * X00.x + cb * X01.x, sb * X00.y + cb * X01.y);
        float2 M11 = make_float2(sb * X01.x + cb * X00.x, sb * X01.y + cb * X00.y);
        float2 em = make_float2(cg, -sg), ep = make_float2(cg, sg);
        Usm[l][q][0] = cmul(em, M00);
        Usm[l][q][1] = cmul(em, M01);
        Usm[l][q][2] = cmul(ep, M10);
        Usm[l][q][3] = cmul(ep, M11);
    }
    // ---------- encoding dots: 2 batches x 16 q x 4 quarters ----------
    {
        int b = tid >> 6, rest = tid & 63;
        int q = rest >> 2, quarter = rest & 3;
        int eb = blockIdx.x * 2 + b;
        float acc = 0.f;
        if (eb < B) {
            const float4* cr = (const float4*)(ctx + (size_t)eb * 256) + quarter * 16;
            const float4* wr = (const float4*)(Wm + (size_t)q * 256) + quarter * 16;
            #pragma unroll
            for (int k = 0; k < 16; ++k) {
                float4 c = cr[k], w = wr[k];
                acc = fmaf(c.x, w.x, acc); acc = fmaf(c.y, w.y, acc);
                acc = fmaf(c.z, w.z, acc); acc = fmaf(c.w, w.w, acc);
            }
        }
        acc += __shfl_xor_sync(0xffffffffu, acc, 1);
        acc += __shfl_xor_sync(0xffffffffu, acc, 2);
        if (quarter == 0) pf[b][q] = acc;
    }
    __syncthreads();
    if (tid < 32) {
        int b = tid >> 4, q = tid & 15;
        float ang = 3.14159265358979323846f * tanhf(pf[b][q] + bv[q]);
        float h = 0.5f * ang;
        float2 v0 = make_float2(cosf(h), 0.f);
        float2 v1 = make_float2(0.f, -sinf(h));
        wsm[b][q][0] = cfma(Usm[0][q][1], v1, cmul(Usm[0][q][0], v0));
        wsm[b][q][1] = cfma(Usm[0][q][3], v1, cmul(Usm[0][q][2], v0));
    }
    __syncthreads();

    const int l0 = lane & 1, l1 = (lane >> 1) & 1;
    const int l2 = (lane >> 2) & 1, l3 = (lane >> 3) & 1;
    const float sgn = (lane & 16) ? -1.f : 1.f;

    PEnv E;
    if (role == 0) { E.R0 = pk2(lane == 0 ? 1.f : 0.f, 0.f); E.I0 = 0; E.R1 = 0; E.I1 = 0; }
    else           { E.R0 = pk2(1.f, 1.f); E.R1 = pk2(1.f, 1.f); E.I0 = 0; E.I1 = 0; }

    #pragma unroll 1
    for (int i = 0; i < 16; ++i) {
        if (act && role == 0) {
            // ---- Z_{i-1} from E (= L_i) and stored R_i (slot i-1), i >= 8 ----
            if (i >= 8) {
                float4 F0 = Hist[wb][i - 1][0][lane];
                float4 F1 = Hist[wb][i - 1][1][lane];
                u64 OR0 = pk2(F0.x, F0.y), OI0 = pk2(F0.z, F0.w);
                u64 OR1 = pk2(F1.x, F1.y), OI1 = pk2(F1.z, F1.w);
                u64 P = ffma2(E.R1, OR1, fmul2(E.R0, OR0));
                u64 N = ffma2(E.I1, OI1, fmul2(E.I0, OI0));
                float2 p = up2(P), n = up2(N);
                float z = sgn * ((p.x + p.y) - (n.x + n.y));
                #pragma unroll
                for (int o = 16; o; o >>= 1) z += __shfl_xor_sync(0xffffffffu, z, o);
                if (lane == 0) out[(size_t)bat * 16 + (i - 1)] = z;
            }
            // ---- transfer site q = i ----
            const int q = i;
            float2 w0 = wsm[wb][q][0], w1 = wsm[wb][q][1];
            const float2* U2 = Usm[1][q];
            const float2* U3 = Usm[2][q];
            const float2* U4 = Usm[3][q];
            pket_in(E, w0, w1);
            pbra_in(E, w0, w1);
            pket_lane(E, 1, U2[0], U2[2], U2[1], U2[3]);
            pbra_lane(E, 2, U2[0], U2[2], U2[1], U2[3]);
            pket_lane(E, 4, U3[l0], U3[2 | l0], U3[l0], U3[2 | l0]);
            pbra_lane(E, 8, U3[l1], U3[2 | l1], U3[l1], U3[2 | l1]);
            float2 G0 = cmulc(U4[l2], U4[l3]);
            float2 G1 = cmulc(U4[2 | l2], U4[2 | l3]);
            pket_lane(E, 16, G0, G1, G0, G1);
            if (i <= 6) {  // store L_{i+1} to slot i
                float2 r0 = up2(E.R0), i0 = up2(E.I0);
                float2 r1 = up2(E.R1), i1 = up2(E.I1);
                Hist[wb][i][0][lane] = make_float4(r0.x, r0.y, i0.x, i0.y);
                Hist[wb][i][1][lane] = make_float4(r1.x, r1.y, i1.x, i1.y);
            }
        } else if (act && role == 1 && i < 15) {
            // ---- transfer site q = 15 - i (reverse pass order) ----
            const int q = 15 - i;
            float2 w0 = wsm[wb][q][0], w1 = wsm[wb][q][1];
            const float2* U2 = Usm[1][q];
            const float2* U3 = Usm[2][q];
            const float2* U4 = Usm[3][q];
            float2 G0 = cmulc(U4[l2], U4[l3]);
            float2 G1 = cmulc(U4[2 | l2], U4[2 | l3]);
            pket_lane(E, 16, G0, G1, G0, G1);
            pket_lane(E, 4, U3[l0], U3[2 | l0], U3[l0], U3[2 | l0]);
            pbra_lane(E, 8, U3[l1], U3[2 | l1], U3[l1], U3[2 | l1]);
            pket_lane(E, 1, U2[0], U2[2], U2[1], U2[3]);
            pbra_lane(E, 2, U2[0], U2[2], U2[1], U2[3]);
            pket_in(E, w0, w1);
            pbra_in(E, w0, w1);
            if (i <= 7) {  // store R_{15-i} to slot 14-i
                float2 r0 = up2(E.R0), i0 = up2(E.I0);
                float2 r1 = up2(E.R1), i1 = up2(E.I1);
                Hist[wb][14 - i][0][lane] = make_float4(r0.x, r0.y, i0.x, i0.y);
                Hist[wb][14 - i][1][lane] = make_float4(r1.x, r1.y, i1.x, i1.y);
            }
            if (i >= 8) {
                // ---- Z_{14-i} from E (= R_{15-i}) and stored L_{15-i} (slot 14-i) ----
                float4 F0 = Hist[wb][14 - i][0][lane];
                float4 F1 = Hist[wb][14 - i][1][lane];
                u64 OR0 = pk2(F0.x, F0.y), OI0 = pk2(F0.z, F0.w);
                u64 OR1 = pk2(F1.x, F1.y), OI1 = pk2(F1.z, F1.w);
                u64 P = ffma2(E.R1, OR1, fmul2(E.R0, OR0));
                u64 N = ffma2(E.I1, OI1, fmul2(E.I0, OI0));
                float2 p = up2(P), n = up2(N);
                float z = sgn * ((p.x + p.y) - (n.x + n.y));
                #pragma unroll
                for (int o = 16; o; o >>= 1) z += __shfl_xor_sync(0xffffffffu, z, o);
                if (lane == 0) out[(size_t)bat * 16 + (14 - i)] = z;
            }
        }
        __syncthreads();
    }

    // ---- epilogue: Z_15 from E (= L_16) and R_16 = all-ones ----
    if (act && role == 0) {
        float2 r0 = up2(E.R0), r1 = up2(E.R1);
        float z = sgn * (r0.x + r0.y + r1.x + r1.y);
        #pragma unroll
        for (int o = 16; o; o >>= 1) z += __shfl_xor_sync(0xffffffffu, z, o);
        if (lane == 0) out[(size_t)bat * 16 + 15] = z;
    }
}

extern "C" void kernel_launch(void* const* d_in, const int* in_sizes, int n_in,
                              void* d_out, int out_size) {
    const float* ctx = nullptr;
    const float* Wm  = nullptr;
    const float* bv  = nullptr;
    const float* prm = nullptr;
    for (int i = 0; i < n_in; ++i) {
        int sz = in_sizes[i];
        const float* p = (const float*)d_in[i];
        if (sz == 16)        bv  = p;
        else if (sz == 192)  prm = p;
        else if (sz == 4096) Wm  = p;
        else                 ctx = p;  // B*256
    }
    if (!ctx) ctx = (const float*)d_in[0];
    if (!Wm)  Wm  = (const float*)d_in[1];
    if (!bv)  bv  = (const float*)d_in[2];
    if (!prm) prm = (const float*)d_in[3];

    float* out = (float*)d_out;
    int B = out_size / 16;
    if (B <= 0) return;
    int blocks = (B + 1) / 2;
    pqc_mps_kernel<<<blocks, 128>>>(ctx, Wm, bv, prm, out, B);
}